// round 5
// baseline (speedup 1.0000x reference)
#include <cuda_runtime.h>
#include <cstdint>

// Problem constants (from reference: B, S, D = 16, 4096, 512)
#define BB 16
#define SS 4096
#define DD 512
#define ROWBYTES (DD * 4)   // 2048 bytes per row

#define NSLOT 16            // SMEM ring slots
#define DEPTH 8             // loads run this many rows ahead of stores
#define GRID_GATHER 592     // 148 SMs x 4 blocks

// Scratch — per-batch compacted source indices + counts
__device__ int g_src[BB * SS];
__device__ int g_counts[BB];

static __device__ __forceinline__ uint32_t smem_u32(const void* p) {
    uint32_t a;
    asm("{ .reg .u64 t; cvta.to.shared.u64 t, %1; cvt.u32.u64 %0, t; }"
        : "=r"(a) : "l"(p));
    return a;
}

// ---------------------------------------------------------------------------
// Kernel 1: per-batch stable compaction index build + mask output.
// ---------------------------------------------------------------------------
__global__ void __launch_bounds__(1024)
scan_kernel(const float4* __restrict__ probs4, const float4* __restrict__ uniform4,
            float* __restrict__ out_mask, int max_length) {
    const int b = blockIdx.x;
    const int t = threadIdx.x;
    const int idx4 = b * (SS / 4) + t;

    float4 p = probs4[idx4];
    float4 u = uniform4[idx4];

    int keep[4];
    keep[0] = (u.x >= p.x) ? 1 : 0;
    keep[1] = (u.y >= p.y) ? 1 : 0;
    keep[2] = (u.z >= p.z) ? 1 : 0;
    keep[3] = (u.w >= p.w) ? 1 : 0;
    int local = keep[0] + keep[1] + keep[2] + keep[3];

    const int lane = t & 31;
    const int warp = t >> 5;
    int v = local;
#pragma unroll
    for (int o = 1; o < 32; o <<= 1) {
        int uu = __shfl_up_sync(0xffffffffu, v, o);
        if (lane >= o) v += uu;
    }
    __shared__ int warp_sums[32];
    __shared__ int s_total;
    if (lane == 31) warp_sums[warp] = v;
    __syncthreads();
    if (warp == 0) {
        int w = warp_sums[lane];
#pragma unroll
        for (int o = 1; o < 32; o <<= 1) {
            int uu = __shfl_up_sync(0xffffffffu, w, o);
            if (lane >= o) w += uu;
        }
        warp_sums[lane] = w;
        if (lane == 31) s_total = w;
    }
    __syncthreads();

    int excl = v - local + (warp > 0 ? warp_sums[warp - 1] : 0);

    int r = excl;
#pragma unroll
    for (int i = 0; i < 4; i++) {
        if (keep[i]) {
            g_src[b * SS + r] = t * 4 + i;
            r++;
        }
    }

    const int count = s_total;
    if (t == 0) g_counts[b] = count;

    float* mrow = out_mask + (long long)b * max_length;
    for (int j = t; j < max_length; j += 1024) {
        mrow[j] = (j < count) ? 1.0f : 0.0f;
    }
}

// ---------------------------------------------------------------------------
// Kernel 2: gather + pad via cp.async.bulk (TMA bulk DMA) pipeline.
// One 32-thread block handles a strided set of output rows. 16-slot x 2KB
// SMEM ring; single lane issues G->S bulk loads (mbarrier complete_tx) DEPTH
// rows ahead of S->G bulk stores (bulk groups). Padding rows store from a
// pre-zeroed SMEM buffer. No register-path data movement at all.
// ---------------------------------------------------------------------------
__global__ void __launch_bounds__(32)
gather_tma_kernel(const float* __restrict__ x,
                  float* __restrict__ out_padded,
                  int max_length, int total_rows) {
    __shared__ alignas(1024) char ring[NSLOT][ROWBYTES];
    __shared__ alignas(128)  char zbuf[ROWBYTES];
    __shared__ alignas(8)    uint64_t mbar[NSLOT];
    __shared__ int s_counts[BB];

    const int t = threadIdx.x;

    // Zero-fill the pad buffer (generic proxy), preload counts, init mbarriers.
    float4* z4 = reinterpret_cast<float4*>(zbuf);
#pragma unroll
    for (int i = t; i < ROWBYTES / 16; i += 32) z4[i] = make_float4(0.f, 0.f, 0.f, 0.f);
    if (t < BB) s_counts[t] = g_counts[t];
    if (t == 0) {
#pragma unroll
        for (int s = 0; s < NSLOT; s++) {
            uint32_t mb = smem_u32(&mbar[s]);
            asm volatile("mbarrier.init.shared.b64 [%0], 1;" :: "r"(mb) : "memory");
        }
    }
    // Make generic-proxy zbuf writes visible to the async proxy (TMA store reads).
    asm volatile("fence.proxy.async.shared::cta;" ::: "memory");
    __syncwarp();

    if (t != 0) return;   // single-lane pipeline

    const int bx = blockIdx.x;
    const int gd = gridDim.x;
    const int n  = (total_rows - bx + gd - 1) / gd;   // rows for this block
    if (n <= 0) return;

    const uint32_t zb = smem_u32(zbuf);
    uint32_t phasemask = 0;   // per-slot mbarrier phase parity bits

    // kept-row test + bulk-load issue for pipeline step k
    auto issue_load = [&](int k) {
        const int row = bx + k * gd;
        const int b = row / max_length;
        const int j = row - b * max_length;
        if (j >= s_counts[b]) return;                 // pad row: no load
        const int slot = k & (NSLOT - 1);
        const int s = __ldg(&g_src[b * SS + j]);
        const float* src = x + ((long long)b * SS + s) * DD;
        const uint32_t mb = smem_u32(&mbar[slot]);
        const uint32_t dst = smem_u32(ring[slot]);
        asm volatile("mbarrier.arrive.expect_tx.shared.b64 _, [%0], %1;"
                     :: "r"(mb), "r"((uint32_t)ROWBYTES) : "memory");
        asm volatile("cp.async.bulk.shared::cta.global.mbarrier::complete_tx::bytes "
                     "[%0], [%1], %2, [%3];"
                     :: "r"(dst), "l"(src), "r"((uint32_t)ROWBYTES), "r"(mb)
                     : "memory");
    };

    // Prologue: fill pipeline with the first DEPTH loads.
    const int pro = (n < DEPTH) ? n : DEPTH;
    for (int k = 0; k < pro; k++) issue_load(k);

    for (int k = 0; k < n; k++) {
        const int row = bx + k * gd;
        const int b = row / max_length;
        const int j = row - b * max_length;
        const int slot = k & (NSLOT - 1);
        const bool kept = (j < s_counts[b]);

        uint32_t srcbuf = zb;
        if (kept) {
            // Wait for this slot's load (parity from phase bitmask).
            const uint32_t mb = smem_u32(&mbar[slot]);
            const uint32_t ph = (phasemask >> slot) & 1u;
            asm volatile(
                "{\n\t"
                ".reg .pred P;\n\t"
                "WL_%=:\n\t"
                "mbarrier.try_wait.parity.shared.b64 P, [%0], %1, 0x989680;\n\t"
                "@P bra.uni WD_%=;\n\t"
                "bra.uni WL_%=;\n\t"
                "WD_%=:\n\t"
                "}"
                :: "r"(mb), "r"(ph) : "memory");
            phasemask ^= (1u << slot);
            srcbuf = smem_u32(ring[slot]);
        }

        // Bulk store SMEM -> GMEM, one group per row.
        const float* dst = out_padded + (long long)row * DD;
        asm volatile("cp.async.bulk.global.shared::cta.bulk_group [%0], [%1], %2;"
                     :: "l"(dst), "r"(srcbuf), "r"((uint32_t)ROWBYTES) : "memory");
        asm volatile("cp.async.bulk.commit_group;" ::: "memory");

        // Refill: row k+DEPTH reuses slot (k+DEPTH)%NSLOT, last used by store
        // k+DEPTH-NSLOT. wait_group.read(NSLOT-DEPTH) guarantees all stores
        // through k-(NSLOT-DEPTH) have finished READING their SMEM slot.
        const int k2 = k + DEPTH;
        if (k2 < n) {
            asm volatile("cp.async.bulk.wait_group.read %0;"
                         :: "n"(NSLOT - DEPTH) : "memory");
            issue_load(k2);
        }
    }

    // Drain all outstanding bulk stores before kernel exit.
    asm volatile("cp.async.bulk.wait_group 0;" ::: "memory");
}

// ---------------------------------------------------------------------------
// Launch: out_size = B*ML*(D+1)  =>  ML = out_size / (B*(D+1))
// ---------------------------------------------------------------------------
extern "C" void kernel_launch(void* const* d_in, const int* in_sizes, int n_in,
                              void* d_out, int out_size) {
    const float* x       = (const float*)d_in[0];
    const float* probs   = (const float*)d_in[1];
    const float* uniform = (const float*)d_in[2];
    float* out = (float*)d_out;

    const int max_length = out_size / (BB * (DD + 1));
    float* out_mask = out + (long long)BB * max_length * DD;
    const int total_rows = BB * max_length;

    scan_kernel<<<BB, 1024>>>((const float4*)probs, (const float4*)uniform,
                              out_mask, max_length);

    gather_tma_kernel<<<GRID_GATHER, 32>>>(x, out, max_length, total_rows);
}

// round 6
// speedup vs baseline: 1.7938x; 1.7938x over previous
#include <cuda_runtime.h>
#include <cstdint>

// Problem constants (from reference: B, S, D = 16, 4096, 512)
#define BB 16
#define SS 4096
#define DD 512
#define ROWBYTES (DD * 4)      // 2048 bytes per row
#define WPB 8                  // warps per block
#define GRID_GATHER 888        // 148 SMs x 6 blocks (smem-limited single wave)

// Scratch — per-batch compacted source indices + counts
__device__ int g_src[BB * SS];
__device__ int g_counts[BB];

static __device__ __forceinline__ uint32_t smem_u32(const void* p) {
    uint32_t a;
    asm("{ .reg .u64 t; cvta.to.shared.u64 t, %1; cvt.u32.u64 %0, t; }"
        : "=r"(a) : "l"(p));
    return a;
}

// ---------------------------------------------------------------------------
// Kernel 1: per-batch stable compaction index build + mask output.
// ---------------------------------------------------------------------------
__global__ void __launch_bounds__(1024)
scan_kernel(const float4* __restrict__ probs4, const float4* __restrict__ uniform4,
            float* __restrict__ out_mask, int max_length) {
    const int b = blockIdx.x;
    const int t = threadIdx.x;
    const int idx4 = b * (SS / 4) + t;

    float4 p = probs4[idx4];
    float4 u = uniform4[idx4];

    int keep[4];
    keep[0] = (u.x >= p.x) ? 1 : 0;
    keep[1] = (u.y >= p.y) ? 1 : 0;
    keep[2] = (u.z >= p.z) ? 1 : 0;
    keep[3] = (u.w >= p.w) ? 1 : 0;
    int local = keep[0] + keep[1] + keep[2] + keep[3];

    const int lane = t & 31;
    const int warp = t >> 5;
    int v = local;
#pragma unroll
    for (int o = 1; o < 32; o <<= 1) {
        int uu = __shfl_up_sync(0xffffffffu, v, o);
        if (lane >= o) v += uu;
    }
    __shared__ int warp_sums[32];
    __shared__ int s_total;
    if (lane == 31) warp_sums[warp] = v;
    __syncthreads();
    if (warp == 0) {
        int w = warp_sums[lane];
#pragma unroll
        for (int o = 1; o < 32; o <<= 1) {
            int uu = __shfl_up_sync(0xffffffffu, w, o);
            if (lane >= o) w += uu;
        }
        warp_sums[lane] = w;
        if (lane == 31) s_total = w;
    }
    __syncthreads();

    int excl = v - local + (warp > 0 ? warp_sums[warp - 1] : 0);

    int r = excl;
#pragma unroll
    for (int i = 0; i < 4; i++) {
        if (keep[i]) {
            g_src[b * SS + r] = t * 4 + i;
            r++;
        }
    }

    const int count = s_total;
    if (t == 0) g_counts[b] = count;

    float* mrow = out_mask + (long long)b * max_length;
    for (int j = t; j < max_length; j += 1024) {
        mrow[j] = (j < count) ? 1.0f : 0.0f;
    }
}

// ---------------------------------------------------------------------------
// Kernel 2: hybrid gather. Reads: LDG.128 (mostly L2-resident x). Writes:
// SMEM staging + cp.async.bulk S->G — one 2KB DMA burst per output row,
// instead of interleaved 512B STG pieces from thousands of warps (DRAM
// row-buffer friendly). 8 independent warp-pipelines per block, 2-slot
// double buffer each; wait_group.read 1 bounds slot reuse (smem-read side
// completes fast, so this rarely blocks).
// ---------------------------------------------------------------------------
__global__ void __launch_bounds__(256)
gather_kernel(const float* __restrict__ x,
              float* __restrict__ out_padded,
              int max_length, int total_rows) {
    __shared__ alignas(128) float4 ring[WPB][2][DD / 4];  // 8 x 2 x 2KB = 32KB
    __shared__ int s_counts[BB];

    if (threadIdx.x < BB) s_counts[threadIdx.x] = g_counts[threadIdx.x];
    __syncthreads();

    const int lane = threadIdx.x & 31;
    const int w    = threadIdx.x >> 5;
    const int gw   = blockIdx.x * WPB + w;     // global warp id
    const int nw   = gridDim.x * WPB;          // total warps

    int it = 0;
    for (int row = gw; row < total_rows; row += nw, ++it) {
        const int slot = it & 1;
        float4* buf = ring[w][slot];

        // Before reusing this slot, ensure the bulk store issued 2 iterations
        // ago has finished READING it (wait_group.read: source-side completion).
        if (it >= 2) {
            if (lane == 0)
                asm volatile("cp.async.bulk.wait_group.read 1;" ::: "memory");
            __syncwarp();
        }

        const int b = row / max_length;
        const int j = row - b * max_length;

        float4 v0, v1, v2, v3;
        if (j < s_counts[b]) {
            const int s = __ldg(&g_src[b * SS + j]);
            const float4* src = reinterpret_cast<const float4*>(
                x + ((long long)b * SS + s) * DD);
            v0 = __ldcg(src + lane);
            v1 = __ldcg(src + lane + 32);
            v2 = __ldcg(src + lane + 64);
            v3 = __ldcg(src + lane + 96);
        } else {
            v0 = v1 = v2 = v3 = make_float4(0.f, 0.f, 0.f, 0.f);
        }
        buf[lane]      = v0;
        buf[lane + 32] = v1;
        buf[lane + 64] = v2;
        buf[lane + 96] = v3;

        // Order generic-proxy STS before async-proxy (TMA) read, warp-wide.
        asm volatile("fence.proxy.async.shared::cta;" ::: "memory");
        __syncwarp();

        if (lane == 0) {
            const float* dst = out_padded + (long long)row * DD;
            const uint32_t sb = smem_u32(buf);
            asm volatile("cp.async.bulk.global.shared::cta.bulk_group [%0], [%1], %2;"
                         :: "l"(dst), "r"(sb), "r"((uint32_t)ROWBYTES) : "memory");
            asm volatile("cp.async.bulk.commit_group;" ::: "memory");
        }
    }

    // Drain all outstanding bulk stores before exit.
    if (lane == 0)
        asm volatile("cp.async.bulk.wait_group 0;" ::: "memory");
}

// ---------------------------------------------------------------------------
// Launch: out_size = B*ML*(D+1)  =>  ML = out_size / (B*(D+1))
// ---------------------------------------------------------------------------
extern "C" void kernel_launch(void* const* d_in, const int* in_sizes, int n_in,
                              void* d_out, int out_size) {
    const float* x       = (const float*)d_in[0];
    const float* probs   = (const float*)d_in[1];
    const float* uniform = (const float*)d_in[2];
    float* out = (float*)d_out;

    const int max_length = out_size / (BB * (DD + 1));
    float* out_mask = out + (long long)BB * max_length * DD;
    const int total_rows = BB * max_length;

    scan_kernel<<<BB, 1024>>>((const float4*)probs, (const float4*)uniform,
                              out_mask, max_length);

    gather_kernel<<<GRID_GATHER, 256>>>(x, out, max_length, total_rows);
}

// round 7
// speedup vs baseline: 2.1558x; 1.2018x over previous
#include <cuda_runtime.h>

// Problem constants (from reference: B, S, D = 16, 4096, 512)
#define BB 16
#define SS 4096
#define DD 512

// Scratch — per-batch compacted source indices + counts
__device__ int g_src[BB * SS];
__device__ int g_counts[BB];

// ---------------------------------------------------------------------------
// Kernel 1: per-batch stable compaction index build + mask output.
// ---------------------------------------------------------------------------
__global__ void __launch_bounds__(1024)
scan_kernel(const float4* __restrict__ probs4, const float4* __restrict__ uniform4,
            float* __restrict__ out_mask, int max_length) {
    const int b = blockIdx.x;
    const int t = threadIdx.x;
    const int idx4 = b * (SS / 4) + t;

    float4 p = probs4[idx4];
    float4 u = uniform4[idx4];

    int keep[4];
    keep[0] = (u.x >= p.x) ? 1 : 0;
    keep[1] = (u.y >= p.y) ? 1 : 0;
    keep[2] = (u.z >= p.z) ? 1 : 0;
    keep[3] = (u.w >= p.w) ? 1 : 0;
    int local = keep[0] + keep[1] + keep[2] + keep[3];

    const int lane = t & 31;
    const int warp = t >> 5;
    int v = local;
#pragma unroll
    for (int o = 1; o < 32; o <<= 1) {
        int uu = __shfl_up_sync(0xffffffffu, v, o);
        if (lane >= o) v += uu;
    }
    __shared__ int warp_sums[32];
    __shared__ int s_total;
    if (lane == 31) warp_sums[warp] = v;
    __syncthreads();
    if (warp == 0) {
        int w = warp_sums[lane];
#pragma unroll
        for (int o = 1; o < 32; o <<= 1) {
            int uu = __shfl_up_sync(0xffffffffu, w, o);
            if (lane >= o) w += uu;
        }
        warp_sums[lane] = w;
        if (lane == 31) s_total = w;
    }
    __syncthreads();

    int excl = v - local + (warp > 0 ? warp_sums[warp - 1] : 0);

    int r = excl;
#pragma unroll
    for (int i = 0; i < 4; i++) {
        if (keep[i]) {
            g_src[b * SS + r] = t * 4 + i;
            r++;
        }
    }

    const int count = s_total;
    if (t == 0) g_counts[b] = count;

    // Mask row for this batch (default policy: small, let it live in L2).
    float* mrow = out_mask + (long long)b * max_length;
    for (int j = t; j < max_length; j += 1024) {
        mrow[j] = (j < count) ? 1.0f : 0.0f;
    }
}

// ---------------------------------------------------------------------------
// Kernel 2: gather + pad. Persistent grid, one row per warp per iteration,
// MLP=4 LDG.128 front-batched.
// L2 policy FLIP vs R4: x reads are evict-first (__ldcs) so they never
// displace output lines; output stores are DEFAULT write-back so the 67MB
// output stays L2-resident across graph replays — DRAM then carries an
// (almost) pure read stream of x instead of a mixed R/W stream.
// ---------------------------------------------------------------------------
__global__ void __launch_bounds__(256, 8)
gather_kernel(const float* __restrict__ x,
              float* __restrict__ out_padded,
              int max_length, int total_rows) {
    __shared__ int s_counts[BB];
    if (threadIdx.x < BB) s_counts[threadIdx.x] = g_counts[threadIdx.x];
    __syncthreads();

    const int lane = threadIdx.x & 31;
    const int gw   = blockIdx.x * 8 + (threadIdx.x >> 5);  // global warp id
    const int nw   = gridDim.x * 8;                        // total warps

    for (int row = gw; row < total_rows; row += nw) {
        const int b = row / max_length;
        const int j = row - b * max_length;

        float4* dst = reinterpret_cast<float4*>(out_padded + (long long)row * DD);

        if (j < s_counts[b]) {
            const int s = __ldg(&g_src[b * SS + j]);
            const float4* src = reinterpret_cast<const float4*>(
                x + ((long long)b * SS + s) * DD);
            float4 v0 = __ldcs(src + lane);
            float4 v1 = __ldcs(src + lane + 32);
            float4 v2 = __ldcs(src + lane + 64);
            float4 v3 = __ldcs(src + lane + 96);
            dst[lane]      = v0;
            dst[lane + 32] = v1;
            dst[lane + 64] = v2;
            dst[lane + 96] = v3;
        } else {
            const float4 z = make_float4(0.f, 0.f, 0.f, 0.f);
            dst[lane]      = z;
            dst[lane + 32] = z;
            dst[lane + 64] = z;
            dst[lane + 96] = z;
        }
    }
}

// ---------------------------------------------------------------------------
// Launch: out_size = B*ML*(D+1)  =>  ML = out_size / (B*(D+1))
// ---------------------------------------------------------------------------
extern "C" void kernel_launch(void* const* d_in, const int* in_sizes, int n_in,
                              void* d_out, int out_size) {
    const float* x       = (const float*)d_in[0];
    const float* probs   = (const float*)d_in[1];
    const float* uniform = (const float*)d_in[2];
    float* out = (float*)d_out;

    const int max_length = out_size / (BB * (DD + 1));
    float* out_mask = out + (long long)BB * max_length * DD;
    const int total_rows = BB * max_length;

    scan_kernel<<<BB, 1024>>>((const float4*)probs, (const float4*)uniform,
                              out_mask, max_length);

    const int blocks = 1184;  // 148 SMs x 8 blocks (persistent single wave)
    gather_kernel<<<blocks, 256>>>(x, out, max_length, total_rows);
}

// round 8
// speedup vs baseline: 2.1586x; 1.0013x over previous
#include <cuda_runtime.h>
#include <cstdint>

// Problem constants (from reference: B, S, D = 16, 4096, 512)
#define BB 16
#define SS 4096
#define DD 512
#define GRID_FUSED 1184   // 148 SMs x 8 blocks

// Scratch — per-batch compacted source indices + counts, plus sync state.
__device__ int g_src[BB * SS];
__device__ int g_counts[BB];
__device__ int g_ready;   // zero-initialized; reset by last block each launch
__device__ int g_done;

static __device__ __forceinline__ int ld_acquire(const int* p) {
    int v;
    asm volatile("ld.acquire.gpu.b32 %0, [%1];" : "=r"(v) : "l"(p) : "memory");
    return v;
}

// ---------------------------------------------------------------------------
// Fused kernel.
// Phase 1 (blocks 0..15): per-batch stable compaction scan. 256 threads x 16
//   elements. Block exclusive scan of keep flags -> packed ranks into g_src,
//   count into g_counts, mask row written directly. Release via g_ready.
// Barrier: all blocks spin until all 16 scans are published.
// Phase 2 (all blocks): persistent gather, one row per warp per iteration,
//   4x LDG.128 front-batched. This phase sits on the LTS cap (~6300 B/cyc,
//   136.5 MB compulsory L2 traffic) — structure beyond coalescing is moot.
// Epilogue: last block resets sync state for graph replay determinism.
// ---------------------------------------------------------------------------
__global__ void __launch_bounds__(256, 8)
fused_kernel(const float* __restrict__ x,
             const float4* __restrict__ probs4,
             const float4* __restrict__ uniform4,
             float* __restrict__ out_padded,
             float* __restrict__ out_mask,
             int max_length, int total_rows) {
    const int t = threadIdx.x;
    __shared__ int s_counts[BB];

    // ---------------- Phase 1: scan (blocks 0..15 only) ----------------
    if (blockIdx.x < BB) {
        const int b = blockIdx.x;
        // 16 elements per thread = 4 float4 of probs + 4 of uniform.
        const int base4 = b * (SS / 4) + t * 4;

        int keep[16];
        int local = 0;
#pragma unroll
        for (int q = 0; q < 4; q++) {
            float4 p = probs4[base4 + q];
            float4 u = uniform4[base4 + q];
            keep[q * 4 + 0] = (u.x >= p.x) ? 1 : 0;
            keep[q * 4 + 1] = (u.y >= p.y) ? 1 : 0;
            keep[q * 4 + 2] = (u.z >= p.z) ? 1 : 0;
            keep[q * 4 + 3] = (u.w >= p.w) ? 1 : 0;
            local += keep[q * 4 + 0] + keep[q * 4 + 1]
                   + keep[q * 4 + 2] + keep[q * 4 + 3];
        }

        const int lane = t & 31;
        const int warp = t >> 5;
        int v = local;
#pragma unroll
        for (int o = 1; o < 32; o <<= 1) {
            int uu = __shfl_up_sync(0xffffffffu, v, o);
            if (lane >= o) v += uu;
        }
        __shared__ int warp_sums[8];
        __shared__ int s_total;
        if (lane == 31) warp_sums[warp] = v;
        __syncthreads();
        if (warp == 0 && lane < 8) {
            int w = warp_sums[lane];
#pragma unroll
            for (int o = 1; o < 8; o <<= 1) {
                int uu = __shfl_up_sync(0x000000ffu, w, o);
                if (lane >= o) w += uu;
            }
            warp_sums[lane] = w;
            if (lane == 7) s_total = w;
        }
        __syncthreads();

        int excl = v - local + (warp > 0 ? warp_sums[warp - 1] : 0);

        int r = excl;
#pragma unroll
        for (int i = 0; i < 16; i++) {
            if (keep[i]) {
                g_src[b * SS + r] = t * 16 + i;
                r++;
            }
        }

        const int count = s_total;
        if (t == 0) g_counts[b] = count;

        // Mask row for this batch.
        float* mrow = out_mask + (long long)b * max_length;
        for (int j = t; j < max_length; j += 256) {
            mrow[j] = (j < count) ? 1.0f : 0.0f;
        }

        // Publish this batch's scan.
        __syncthreads();
        if (t == 0) {
            __threadfence();
            atomicAdd(&g_ready, 1);
        }
    }

    // ---------------- Barrier: wait for all 16 scans ----------------
    if (t == 0) {
        while (ld_acquire(&g_ready) < BB) {
            __nanosleep(64);
        }
    }
    __syncthreads();

    if (t < BB) s_counts[t] = g_counts[t];
    __syncthreads();

    // ---------------- Phase 2: persistent gather ----------------
    const int lane = t & 31;
    const int gw   = blockIdx.x * 8 + (t >> 5);   // global warp id
    const int nw   = gridDim.x * 8;               // total warps

    for (int row = gw; row < total_rows; row += nw) {
        const int b = row / max_length;
        const int j = row - b * max_length;

        float4* dst = reinterpret_cast<float4*>(out_padded + (long long)row * DD);

        if (j < s_counts[b]) {
            const int s = __ldg(&g_src[b * SS + j]);
            const float4* src = reinterpret_cast<const float4*>(
                x + ((long long)b * SS + s) * DD);
            float4 v0 = __ldcg(src + lane);
            float4 v1 = __ldcg(src + lane + 32);
            float4 v2 = __ldcg(src + lane + 64);
            float4 v3 = __ldcg(src + lane + 96);
            __stcs(dst + lane,      v0);
            __stcs(dst + lane + 32, v1);
            __stcs(dst + lane + 64, v2);
            __stcs(dst + lane + 96, v3);
        } else {
            const float4 z = make_float4(0.f, 0.f, 0.f, 0.f);
            __stcs(dst + lane,      z);
            __stcs(dst + lane + 32, z);
            __stcs(dst + lane + 64, z);
            __stcs(dst + lane + 96, z);
        }
    }

    // ---------------- Epilogue: reset sync state for next replay ----------------
    __syncthreads();
    if (t == 0) {
        int old = atomicAdd(&g_done, 1);
        if (old == (int)gridDim.x - 1) {
            g_ready = 0;
            g_done = 0;
        }
    }
}

// ---------------------------------------------------------------------------
// Launch: out_size = B*ML*(D+1)  =>  ML = out_size / (B*(D+1))
// ---------------------------------------------------------------------------
extern "C" void kernel_launch(void* const* d_in, const int* in_sizes, int n_in,
                              void* d_out, int out_size) {
    const float* x       = (const float*)d_in[0];
    const float* probs   = (const float*)d_in[1];
    const float* uniform = (const float*)d_in[2];
    float* out = (float*)d_out;

    const int max_length = out_size / (BB * (DD + 1));
    float* out_mask = out + (long long)BB * max_length * DD;
    const int total_rows = BB * max_length;

    fused_kernel<<<GRID_FUSED, 256>>>(x, (const float4*)probs,
                                      (const float4*)uniform,
                                      out, out_mask, max_length, total_rows);
}